// round 8
// baseline (speedup 1.0000x reference)
#include <cuda_runtime.h>
#include <cuda_bf16.h>
#include <cstdint>

// ============================================================================
// S4D: K[i] = C @ A^i @ B, A diagonal.
//   K[i][m][d] = sum_n C[m][n] * a_n^i * B[n][d]
//   => GEMM: K[4096, 16384] = V[4096, 64] @ W[64, 16384]
// sm_103 generic target -> mma.sync bf16 (HMMA), bf16x3 split
// (hi*hi + hi*lo + lo*hi), operands pre-stored in fragment order.
// R8 = R7 resubmit (infra failure last round): powers via exact fp64 squaring
// table (no fp64 log/exp launch); B tiles cp.async double-buffered in SMEM,
// consumed via LDS.128.
// ============================================================================

#define L_LEN 4096
#define NS 64
#define DM 128
#define COLS_TOTAL (DM * DM)   // 16384

#define N_TILES 4096           // 32 strips x 128 col-tiles (128x128 each)
#define N_CTAS 304             // 2 per SM
#define CHUNK 14               // ceil(4096/304)

// A-fragment arrays: [blkf(256)][ks(4)][lane(32)] uint4; r0 = blkf*16 + lane/4
#define VF_ELEMS (256 * 4 * 32)          // 32768
// B-fragment array (hi/lo interleaved): [nbf(2048)][ks(4)][lane(32)] uint4
//   .x .y = bhi b0,b1 ; .z .w = blo b0,b1 ; col = nbf*8 + lane/4
#define WF_ELEMS (2048 * 4 * 32)         // 262144
#define B_TILE_ELEMS 2048                // uint4 per 128-col tile (32KB)

__device__ uint4 g_VFhi[VF_ELEMS];
__device__ uint4 g_VFlo[VF_ELEMS];
__device__ uint4 g_WF[WF_ELEMS];

__device__ __forceinline__ void mma_16816(float* c, const uint32_t* a,
                                          const uint32_t* b) {
    asm volatile(
        "mma.sync.aligned.m16n8k16.row.col.f32.bf16.bf16.f32 "
        "{%0,%1,%2,%3}, {%4,%5,%6,%7}, {%8,%9}, {%0,%1,%2,%3};"
        : "+f"(c[0]), "+f"(c[1]), "+f"(c[2]), "+f"(c[3])
        : "r"(a[0]), "r"(a[1]), "r"(a[2]), "r"(a[3]), "r"(b[0]), "r"(b[1]));
}

__device__ __forceinline__ uint32_t smem_u32(const void* p) {
    uint32_t a;
    asm("{ .reg .u64 t; cvta.to.shared.u64 t, %1; cvt.u32.u64 %0, t; }"
        : "=r"(a) : "l"(p));
    return a;
}

__device__ __forceinline__ uint32_t pack_bf2(__nv_bfloat16 x, __nv_bfloat16 y) {
    __nv_bfloat162 t(x, y);
    return *(uint32_t*)&t;
}

__device__ __forceinline__ void split2(float v0, float v1,
                                       uint32_t& hi, uint32_t& lo) {
    __nv_bfloat16 h0 = __float2bfloat16(v0);
    __nv_bfloat16 h1 = __float2bfloat16(v1);
    float l0 = v0 - __bfloat162float(h0);
    float l1 = v1 - __bfloat162float(h1);
    hi = pack_bf2(h0, h1);
    lo = pack_bf2(__float2bfloat16(l0), __float2bfloat16(l1));
}

// ============================================================================
// Merged prep: blocks [0,128) build V fragments (via per-block fp64 squaring
// table a^(2^j), exact), blocks [128,1152) build W fragments.
// ============================================================================
#define VF_BLOCKS (VF_ELEMS / 256)       // 128
#define WF_BLOCKS (WF_ELEMS / 256)       // 1024

__global__ void s4d_prep_frag(const float* __restrict__ A,
                              const float* __restrict__ C,
                              const float* __restrict__ Bm) {
    __shared__ double s_p[12][NS];       // a_n^(2^j)

    if (blockIdx.x < VF_BLOCKS) {
        if (threadIdx.x < NS) {
            double p = (double)A[threadIdx.x * (NS + 1)];   // diagonal
            s_p[0][threadIdx.x] = p;
#pragma unroll
            for (int j = 1; j < 12; j++) { p = p * p; s_p[j][threadIdx.x] = p; }
        }
        __syncthreads();

        int idx = blockIdx.x * 256 + threadIdx.x;
        int lane = idx & 31;
        int ks   = (idx >> 5) & 3;
        int blkf = idx >> 7;
        int g  = lane >> 2;
        int tg = lane & 3;
        int r0 = blkf * 16 + g;
        int r1 = r0 + 8;
        int k0 = ks * 16 + tg * 2;

        double acc[2][4];
#pragma unroll
        for (int h = 0; h < 2; h++) {
            int r = h ? r1 : r0;
            double a0 = 1.0, a1 = 1.0, a2 = 1.0, a3 = 1.0;
#pragma unroll
            for (int j = 0; j < 12; j++) {
                if ((r >> j) & 1) {
                    a0 *= s_p[j][k0];
                    a1 *= s_p[j][k0 + 1];
                    a2 *= s_p[j][k0 + 8];
                    a3 *= s_p[j][k0 + 9];
                }
            }
            acc[h][0] = a0; acc[h][1] = a1; acc[h][2] = a2; acc[h][3] = a3;
        }

        uint4 hi, lo;
        split2((float)acc[0][0], (float)acc[0][1], hi.x, lo.x);   // (r0, n0 n1)
        split2((float)acc[1][0], (float)acc[1][1], hi.y, lo.y);   // (r1, n0 n1)
        split2((float)acc[0][2], (float)acc[0][3], hi.z, lo.z);   // (r0, n8 n9)
        split2((float)acc[1][2], (float)acc[1][3], hi.w, lo.w);   // (r1, n8 n9)
        g_VFhi[idx] = hi;
        g_VFlo[idx] = lo;
    } else {
        int idx = (blockIdx.x - VF_BLOCKS) * 256 + threadIdx.x;
        int lane = idx & 31;
        int ks   = (idx >> 5) & 3;
        int nbf  = idx >> 7;
        int g  = lane >> 2;
        int tg = lane & 3;
        int col = nbf * 8 + g;
        int k0  = ks * 16 + tg * 2;
        int m = col >> 7;
        int d = col & 127;

        const float* Crow = C + m * NS;
        float w0 = Crow[k0]     * Bm[k0 * DM + d];
        float w1 = Crow[k0 + 1] * Bm[(k0 + 1) * DM + d];
        float w8 = Crow[k0 + 8] * Bm[(k0 + 8) * DM + d];
        float w9 = Crow[k0 + 9] * Bm[(k0 + 9) * DM + d];

        uint4 w;                          // .xy = hi(b0,b1), .zw = lo(b0,b1)
        split2(w0, w1, w.x, w.z);
        split2(w8, w9, w.y, w.w);
        g_WF[idx] = w;
    }
}

// ============================================================================
// Main: persistent CTAs, CHUNK consecutive col-tiles per CTA (A frags stay
// L1-resident). B tile (32KB, fragment order) cp.async double-buffered in
// SMEM; consumed via conflict-free LDS.128. A via LDG. Streaming stores.
// ============================================================================
__global__ void __launch_bounds__(256, 2) s4d_mma_kernel(float* __restrict__ out) {
    extern __shared__ uint4 sB[];        // [2][B_TILE_ELEMS]
    const uint32_t sb = smem_u32(sB);
    const int tid  = threadIdx.x;
    const int wid  = tid >> 5;
    const int lane = tid & 31;
    const int m_w = (wid & 1) * 64;
    const int n_w = (wid >> 1) * 32;

    const int t0 = blockIdx.x * CHUNK;
    int nTiles = N_TILES - t0;
    if (nTiles <= 0) return;
    if (nTiles > CHUNK) nTiles = CHUNK;

    // ---- prefetch tile 0's B block into buffer 0 ----
    {
        const int bx = t0 & 127;
        const uint4* src = g_WF + (size_t)bx * B_TILE_ELEMS;
#pragma unroll
        for (int k = 0; k < 8; k++) {
            int e = tid + k * 256;
            uint32_t dst = sb + (uint32_t)e * 16u;
            asm volatile("cp.async.cg.shared.global [%0], [%1], 16;"
                         :: "r"(dst), "l"(src + e));
        }
        asm volatile("cp.async.commit_group;");
    }

    for (int j = 0; j < nTiles; j++) {
        const int t = t0 + j;
        const int bx = t & 127;
        const int by = t >> 7;

        asm volatile("cp.async.wait_group 0;");
        __syncthreads();

        // issue next tile's prefetch into the other buffer
        if (j + 1 < nTiles) {
            const int bx2 = (t + 1) & 127;
            const uint4* src = g_WF + (size_t)bx2 * B_TILE_ELEMS;
            const uint32_t dbase = sb + (uint32_t)(((j + 1) & 1) * B_TILE_ELEMS) * 16u;
#pragma unroll
            for (int k = 0; k < 8; k++) {
                int e = tid + k * 256;
                asm volatile("cp.async.cg.shared.global [%0], [%1], 16;"
                             :: "r"(dbase + (uint32_t)e * 16u), "l"(src + e));
            }
            asm volatile("cp.async.commit_group;");
        }

        // A base: ((by*8 + m_w/16 + mi)*4 + ks)*32 + lane
        const int abase = (by * 8 + (m_w >> 4)) * 128 + lane;
        // B smem base for this warp (element units)
        const uint32_t bsm = sb +
            (uint32_t)(((j & 1) * B_TILE_ELEMS) + ((n_w >> 3) * 128) + lane) * 16u;

        float c[4][4][4];
#pragma unroll
        for (int mi = 0; mi < 4; mi++)
#pragma unroll
            for (int ni = 0; ni < 4; ni++)
#pragma unroll
                for (int k = 0; k < 4; k++) c[mi][ni][k] = 0.0f;

#pragma unroll
        for (int ks = 0; ks < 4; ks++) {
            uint4 ahi[4];
            uint4 bw[4];
#pragma unroll
            for (int mi = 0; mi < 4; mi++)
                ahi[mi] = g_VFhi[abase + mi * 128 + ks * 32];
#pragma unroll
            for (int ni = 0; ni < 4; ni++) {
                uint32_t addr = bsm + (uint32_t)((ni * 128 + ks * 32) * 16);
                asm volatile("ld.shared.v4.u32 {%0,%1,%2,%3}, [%4];"
                             : "=r"(bw[ni].x), "=r"(bw[ni].y),
                               "=r"(bw[ni].z), "=r"(bw[ni].w)
                             : "r"(addr));
            }

#pragma unroll
            for (int mi = 0; mi < 4; mi++)
#pragma unroll
                for (int ni = 0; ni < 4; ni++)
                    mma_16816(c[mi][ni], (const uint32_t*)&ahi[mi],
                              (const uint32_t*)&bw[ni].x);     // B hi
#pragma unroll
            for (int mi = 0; mi < 4; mi++)
#pragma unroll
                for (int ni = 0; ni < 4; ni++)
                    mma_16816(c[mi][ni], (const uint32_t*)&ahi[mi],
                              (const uint32_t*)&bw[ni].z);     // B lo

            uint4 alo[4];
#pragma unroll
            for (int mi = 0; mi < 4; mi++)
                alo[mi] = g_VFlo[abase + mi * 128 + ks * 32];
#pragma unroll
            for (int mi = 0; mi < 4; mi++)
#pragma unroll
                for (int ni = 0; ni < 4; ni++)
                    mma_16816(c[mi][ni], (const uint32_t*)&alo[mi],
                              (const uint32_t*)&bw[ni].x);     // B hi
        }

        // ---- epilogue: fragment-direct streaming float2 stores ----
        const int gm = by * 128 + m_w + (lane >> 2);
        const int gn = bx * 128 + n_w + (lane & 3) * 2;
#pragma unroll
        for (int mi = 0; mi < 4; mi++) {
            size_t r0 = (size_t)(gm + mi * 16) * COLS_TOTAL + gn;
            size_t r1 = r0 + (size_t)8 * COLS_TOTAL;
#pragma unroll
            for (int ni = 0; ni < 4; ni++) {
                __stcs((float2*)(out + r0 + ni * 8),
                       make_float2(c[mi][ni][0], c[mi][ni][1]));
                __stcs((float2*)(out + r1 + ni * 8),
                       make_float2(c[mi][ni][2], c[mi][ni][3]));
            }
        }
    }
}

// ============================================================================
// launch
// ============================================================================
extern "C" void kernel_launch(void* const* d_in, const int* in_sizes, int n_in,
                              void* d_out, int out_size) {
    const float* A  = (const float*)d_in[0];   // (64, 64) diagonal
    const float* Bm = (const float*)d_in[1];   // (64, 128)
    const float* C  = (const float*)d_in[2];   // (128, 64)
    float* out = (float*)d_out;                // (4096, 128, 128) fp32

    cudaFuncSetAttribute(s4d_mma_kernel,
                         cudaFuncAttributeMaxDynamicSharedMemorySize,
                         2 * B_TILE_ELEMS * sizeof(uint4));

    s4d_prep_frag<<<VF_BLOCKS + WF_BLOCKS, 256>>>(A, C, Bm);
    s4d_mma_kernel<<<N_CTAS, 256, 2 * B_TILE_ELEMS * sizeof(uint4)>>>(out);
}

// round 10
// speedup vs baseline: 1.7035x; 1.7035x over previous
#include <cuda_runtime.h>
#include <cuda_bf16.h>
#include <cstdint>

// ============================================================================
// S4D: K[i] = C @ A^i @ B, A diagonal.
//   K[i][m][d] = sum_n C[m][n] * a_n^i * B[n][d]
//   => GEMM: K[4096, 16384] = V[4096, 64] @ W[64, 16384]
// sm_103 generic target -> mma.sync bf16 (HMMA), bf16x3 split
// (hi*hi + hi*lo + lo*hi), operands pre-stored in fragment order (no SMEM).
// R9: main kernel reverted to the proven R4 shape (direct LDG fragments,
// grid 4096, no SMEM). Preps fixed: exact fp64 squaring table in a micro
// kernel, V powers as exact fp64 products (no software log/exp).
// ============================================================================

#define L_LEN 4096
#define NS 64
#define DM 128
#define COLS_TOTAL (DM * DM)   // 16384

// A-fragment array: [blkf(256)][ks(4)][lane(32)] uint4 (a0..a3)
//   r0 = blkf*16 + lane/4, r1 = r0+8; n = ks*16 + (lane%4)*2 (+1,+8,+9)
#define VF_ELEMS (256 * 4 * 32)          // 32768
// B-fragment array: [nbf(2048)][ks(4)][lane(32)] uint2 (b0, b1)
//   col = nbf*8 + lane/4; k = ks*16 + (lane%4)*2 (+1,+8,+9)
#define WF_ELEMS (2048 * 4 * 32)         // 262144

__device__ uint4 g_VFhi[VF_ELEMS];
__device__ uint4 g_VFlo[VF_ELEMS];
__device__ uint2 g_WFhi[WF_ELEMS];
__device__ uint2 g_WFlo[WF_ELEMS];
__device__ double g_pw[12 * NS];         // a_n^(2^j), exact fp64

__device__ __forceinline__ void mma_16816(float* c, const uint32_t* a,
                                          const uint32_t* b) {
    asm volatile(
        "mma.sync.aligned.m16n8k16.row.col.f32.bf16.bf16.f32 "
        "{%0,%1,%2,%3}, {%4,%5,%6,%7}, {%8,%9}, {%0,%1,%2,%3};"
        : "+f"(c[0]), "+f"(c[1]), "+f"(c[2]), "+f"(c[3])
        : "r"(a[0]), "r"(a[1]), "r"(a[2]), "r"(a[3]), "r"(b[0]), "r"(b[1]));
}

__device__ __forceinline__ uint32_t pack_bf2(__nv_bfloat16 x, __nv_bfloat16 y) {
    __nv_bfloat162 t(x, y);
    return *(uint32_t*)&t;
}

__device__ __forceinline__ void split2(float v0, float v1,
                                       uint32_t& hi, uint32_t& lo) {
    __nv_bfloat16 h0 = __float2bfloat16(v0);
    __nv_bfloat16 h1 = __float2bfloat16(v1);
    float l0 = v0 - __bfloat162float(h0);
    float l1 = v1 - __bfloat162float(h1);
    hi = pack_bf2(h0, h1);
    lo = pack_bf2(__float2bfloat16(l0), __float2bfloat16(l1));
}

// ============================================================================
// Prep 0: exact fp64 squaring table a_n^(2^j), one tiny block.
// ============================================================================
__global__ void s4d_prep_pows(const float* __restrict__ A) {
    int n = threadIdx.x;
    if (n < NS) {
        double p = (double)A[n * (NS + 1)];   // diagonal entry
        g_pw[n] = p;
#pragma unroll
        for (int j = 1; j < 12; j++) {
            p = p * p;
            g_pw[j * NS + n] = p;
        }
    }
}

// exact a^i as product over set bits of i (i < 4096)
__device__ __forceinline__ double pow_exact(int i, int n) {
    double v = 1.0;
#pragma unroll
    for (int j = 0; j < 12; j++)
        if ((i >> j) & 1) v *= g_pw[j * NS + n];
    return v;
}

// ============================================================================
// Prep 1: V in A-fragment order. One uint4 (hi) + uint4 (lo) per thread.
// ============================================================================
__global__ void s4d_prep_vf() {
    int idx = blockIdx.x * blockDim.x + threadIdx.x;
    if (idx >= VF_ELEMS) return;
    int lane = idx & 31;
    int ks   = (idx >> 5) & 3;
    int blkf = idx >> 7;
    int g  = lane >> 2;
    int tg = lane & 3;
    int r0 = blkf * 16 + g;
    int r1 = r0 + 8;
    int k0 = ks * 16 + tg * 2;

    uint4 hi, lo;
    split2((float)pow_exact(r0, k0), (float)pow_exact(r0, k0 + 1), hi.x, lo.x);
    split2((float)pow_exact(r1, k0), (float)pow_exact(r1, k0 + 1), hi.y, lo.y);
    split2((float)pow_exact(r0, k0 + 8), (float)pow_exact(r0, k0 + 9), hi.z, lo.z);
    split2((float)pow_exact(r1, k0 + 8), (float)pow_exact(r1, k0 + 9), hi.w, lo.w);
    g_VFhi[idx] = hi;
    g_VFlo[idx] = lo;
}

// ============================================================================
// Prep 2: W in B-fragment order. One uint2 (hi) + uint2 (lo) per thread.
// ============================================================================
__global__ void s4d_prep_wf(const float* __restrict__ C, const float* __restrict__ Bm) {
    int idx = blockIdx.x * blockDim.x + threadIdx.x;
    if (idx >= WF_ELEMS) return;
    int lane = idx & 31;
    int ks   = (idx >> 5) & 3;
    int nbf  = idx >> 7;
    int g  = lane >> 2;
    int tg = lane & 3;
    int col = nbf * 8 + g;
    int k0  = ks * 16 + tg * 2;
    int m = col >> 7;
    int d = col & 127;

    const float* Crow = C + m * NS;
    float w0 = Crow[k0]     * Bm[k0 * DM + d];
    float w1 = Crow[k0 + 1] * Bm[(k0 + 1) * DM + d];
    float w8 = Crow[k0 + 8] * Bm[(k0 + 8) * DM + d];
    float w9 = Crow[k0 + 9] * Bm[(k0 + 9) * DM + d];

    uint2 hi, lo;
    split2(w0, w1, hi.x, lo.x);          // b0
    split2(w8, w9, hi.y, lo.y);          // b1
    g_WFhi[idx] = hi;
    g_WFlo[idx] = lo;
}

// ============================================================================
// Main (R4 shape): CTA = 128(i) x 128(col), 8 warps of 64x32. No SMEM.
// Fragments loaded directly with LDG.128/LDG.64 from fragment-order arrays.
// Per k-step: Ahi*(Bhi,Blo) then Alo*Bhi.
// ============================================================================
__global__ void __launch_bounds__(256, 2) s4d_mma_kernel(float* __restrict__ out) {
    const int tid  = threadIdx.x;
    const int wid  = tid >> 5;
    const int lane = tid & 31;
    const int m_w = (wid & 1) * 64;
    const int n_w = (wid >> 1) * 32;

    // fragment base indices (element granularity)
    const int abase = ((blockIdx.y * 8 + (m_w >> 4)) * 4) * 32 + lane;
    const int bbase = ((blockIdx.x * 16 + (n_w >> 3)) * 4) * 32 + lane;

    float c[4][4][4];
#pragma unroll
    for (int mi = 0; mi < 4; mi++)
#pragma unroll
        for (int ni = 0; ni < 4; ni++)
#pragma unroll
            for (int k = 0; k < 4; k++) c[mi][ni][k] = 0.0f;

#pragma unroll
    for (int ks = 0; ks < 4; ks++) {
        uint4 ahi[4];
        uint2 bhi[4], blo[4];
#pragma unroll
        for (int mi = 0; mi < 4; mi++) ahi[mi] = g_VFhi[abase + mi * 128 + ks * 32];
#pragma unroll
        for (int ni = 0; ni < 4; ni++) bhi[ni] = g_WFhi[bbase + ni * 128 + ks * 32];
#pragma unroll
        for (int ni = 0; ni < 4; ni++) blo[ni] = g_WFlo[bbase + ni * 128 + ks * 32];

#pragma unroll
        for (int mi = 0; mi < 4; mi++)
#pragma unroll
            for (int ni = 0; ni < 4; ni++)
                mma_16816(c[mi][ni], (const uint32_t*)&ahi[mi],
                          (const uint32_t*)&bhi[ni]);
#pragma unroll
        for (int mi = 0; mi < 4; mi++)
#pragma unroll
            for (int ni = 0; ni < 4; ni++)
                mma_16816(c[mi][ni], (const uint32_t*)&ahi[mi],
                          (const uint32_t*)&blo[ni]);

        uint4 alo[4];
#pragma unroll
        for (int mi = 0; mi < 4; mi++) alo[mi] = g_VFlo[abase + mi * 128 + ks * 32];
#pragma unroll
        for (int mi = 0; mi < 4; mi++)
#pragma unroll
            for (int ni = 0; ni < 4; ni++)
                mma_16816(c[mi][ni], (const uint32_t*)&alo[mi],
                          (const uint32_t*)&bhi[ni]);
    }

    // ---- epilogue: fragment-direct float2 stores (full 32B sectors) ----
    const int gm = blockIdx.y * 128 + m_w + (lane >> 2);
    const int gn = blockIdx.x * 128 + n_w + (lane & 3) * 2;
#pragma unroll
    for (int mi = 0; mi < 4; mi++) {
        size_t r0 = (size_t)(gm + mi * 16) * COLS_TOTAL + gn;
        size_t r1 = r0 + (size_t)8 * COLS_TOTAL;
#pragma unroll
        for (int ni = 0; ni < 4; ni++) {
            *(float2*)(out + r0 + ni * 8) = make_float2(c[mi][ni][0], c[mi][ni][1]);
            *(float2*)(out + r1 + ni * 8) = make_float2(c[mi][ni][2], c[mi][ni][3]);
        }
    }
}

// ============================================================================
// launch
// ============================================================================
extern "C" void kernel_launch(void* const* d_in, const int* in_sizes, int n_in,
                              void* d_out, int out_size) {
    const float* A  = (const float*)d_in[0];   // (64, 64) diagonal
    const float* Bm = (const float*)d_in[1];   // (64, 128)
    const float* C  = (const float*)d_in[2];   // (128, 64)
    float* out = (float*)d_out;                // (4096, 128, 128) fp32

    s4d_prep_pows<<<1, 64>>>(A);
    s4d_prep_vf<<<VF_ELEMS / 256, 256>>>();
    s4d_prep_wf<<<WF_ELEMS / 256, 256>>>(C, Bm);

    dim3 grid(COLS_TOTAL / 128, L_LEN / 128);  // (128, 32)
    s4d_mma_kernel<<<grid, 256>>>(out);
}